// round 13
// baseline (speedup 1.0000x reference)
#include <cuda_runtime.h>
#include <cuda_bf16.h>
#include <stdint.h>

// Fixed problem shapes
#define M_ROWS   2048
#define N_POOL   4096
#define K_DIM    768
#define EP_LEN   8
#define XB_ELEMS 309854208LL   // 2048*197*768
#define EKV_ELEMS 6291456LL    // 2048*4*768

// GEMM tiling (tensor-core bf16)
#define GBM 128
#define GBN 128
#define GBK 64
#define GEMM_BLOCKS 512        // (2048/128)*(4096/128)
#define N_TILES 32             // N_POOL / GBN

// Copy: exact division — 77,463,552 float4 = 2364 blocks * 256 thr * 128 f4
#define COPY_BLOCKS 2364
#define CPY_PER_THREAD 128     // 16 iterations of 8 (measured-best config)

#define TAU 0.01f              // > 2x worst-case bf16 mma score error (~0.008)

// Device-global scratch (static allocation — allowed)
__device__ float g_rinv[N_POOL];
__device__ __align__(16) __nv_bfloat16 g_nkbf[N_POOL * K_DIM];   // normalized e_k, bf16
__device__ __align__(16) __nv_bfloat16 g_qbf[M_ROWS * K_DIM];    // normalized q, bf16
__device__ float g_scores[(size_t)M_ROWS * N_POOL];              // approx cos sims
__device__ unsigned g_tmax[(size_t)M_ROWS * N_TILES];            // per-(row,tile) max (mono-encoded)

// order-monotonic float encode/decode
__device__ __forceinline__ unsigned enc_mono(float v) {
    unsigned u = __float_as_uint(v);
    return (u & 0x80000000u) ? ~u : (u | 0x80000000u);
}
__device__ __forceinline__ float dec_mono(unsigned u) {
    unsigned orig = (u & 0x80000000u) ? (u & 0x7FFFFFFFu) : ~u;
    return __uint_as_float(orig);
}

// ---------------------------------------------------------------------------
// Kernel 1: normalize e_k / x_querry -> bf16, store 1/||e_k||.  (validated)
// ---------------------------------------------------------------------------
__global__ void __launch_bounds__(256)
prep_kernel(const float* __restrict__ xq, const float* __restrict__ ek)
{
    const int t = threadIdx.x;
    const int warp = (blockIdx.x * blockDim.x + t) >> 5;
    const int lane = t & 31;

    const bool is_ek = (warp < N_POOL);
    const int row = is_ek ? warp : warp - N_POOL;
    const float* src = (is_ek ? ek : xq) + (size_t)row * K_DIM;
    __nv_bfloat16* dst = (is_ek ? g_nkbf : g_qbf) + (size_t)row * K_DIM;

    float4 v[6];
    float s = 0.f;
    #pragma unroll
    for (int i = 0; i < 6; i++) {
        v[i] = ((const float4*)src)[lane + i * 32];
        s += v[i].x*v[i].x + v[i].y*v[i].y + v[i].z*v[i].z + v[i].w*v[i].w;
    }
    #pragma unroll
    for (int o = 16; o; o >>= 1) s += __shfl_xor_sync(0xffffffffu, s, o);
    float rinv = 1.0f / fmaxf(sqrtf(s), 1e-12f);
    if (is_ek && lane == 0) g_rinv[row] = rinv;

    #pragma unroll
    for (int i = 0; i < 6; i++) {
        __nv_bfloat162 lo = __floats2bfloat162_rn(v[i].x * rinv, v[i].y * rinv);
        __nv_bfloat162 hi = __floats2bfloat162_rn(v[i].z * rinv, v[i].w * rinv);
        uint2 u;
        u.x = *(unsigned*)&lo;
        u.y = *(unsigned*)&hi;
        ((uint2*)dst)[lane + i * 32] = u;
    }
}

// ---------------------------------------------------------------------------
// Kernel 2: bf16 mma.sync GEMM -> g_scores, plus per-(row,tile) max via
// SHARED-memory atomics only (no global atomics — the validated-fast shape).
// ---------------------------------------------------------------------------
__global__ void __launch_bounds__(256)
gemm_kernel()
{
    __shared__ __align__(16) __nv_bfloat16 As[GBM * GBK];
    __shared__ __align__(16) __nv_bfloat16 Bs[GBN * GBK];
    __shared__ unsigned sTmax[GBM];
    uint4* As4 = (uint4*)As;
    uint4* Bs4 = (uint4*)Bs;

    const int wid = blockIdx.x;
    const int m_base = (wid & 15) * GBM;
    const int n_base = (wid >> 4) * GBN;
    const int t = threadIdx.x;
    const int warp = t >> 5, lane = t & 31;
    const int wm = warp >> 1, wn = warp & 1;

    if (t < GBM) sTmax[t] = enc_mono(-1e30f);   // visible after first barrier

    const uint4* __restrict__ gA = (const uint4*)g_qbf;   // row stride 96 uint4
    const uint4* __restrict__ gB = (const uint4*)g_nkbf;

    uint32_t asbase = (uint32_t)__cvta_generic_to_shared(As);
    uint32_t bsbase = (uint32_t)__cvta_generic_to_shared(Bs);

    float d[2][8][4];
    #pragma unroll
    for (int i = 0; i < 2; i++)
        #pragma unroll
        for (int j = 0; j < 8; j++)
            #pragma unroll
            for (int q = 0; q < 4; q++) d[i][j][q] = 0.f;

    int ldr[4], ldc[4];
    #pragma unroll
    for (int p = 0; p < 4; p++) {
        int id = p * 256 + t;
        ldr[p] = id >> 3;
        ldc[p] = id & 7;
    }

    uint4 va[4], vb[4];
    #pragma unroll
    for (int p = 0; p < 4; p++) {
        va[p] = gA[(size_t)(m_base + ldr[p]) * 96 + ldc[p]];
        vb[p] = gB[(size_t)(n_base + ldr[p]) * 96 + ldc[p]];
    }

    for (int k0 = 0; k0 < K_DIM; k0 += GBK) {
        __syncthreads();
        #pragma unroll
        for (int p = 0; p < 4; p++) {
            As4[ldr[p] * 8 + (ldc[p] ^ (ldr[p] & 7))] = va[p];
            Bs4[ldr[p] * 8 + (ldc[p] ^ (ldr[p] & 7))] = vb[p];
        }
        __syncthreads();

        if (k0 + GBK < K_DIM) {
            const int kc = (k0 + GBK) >> 3;
            #pragma unroll
            for (int p = 0; p < 4; p++) {
                va[p] = gA[(size_t)(m_base + ldr[p]) * 96 + kc + ldc[p]];
                vb[p] = gB[(size_t)(n_base + ldr[p]) * 96 + kc + ldc[p]];
            }
        }

        #pragma unroll
        for (int ks = 0; ks < 4; ks++) {
            uint32_t a[2][4];
            #pragma unroll
            for (int i = 0; i < 2; i++) {
                int row = wm * 32 + i * 16 + (lane & 15);
                int ch = (ks * 2 + (lane >> 4)) ^ (row & 7);
                uint32_t addr = asbase + row * 128 + (ch << 4);
                asm volatile("ldmatrix.sync.aligned.m8n8.x4.shared.b16 {%0,%1,%2,%3}, [%4];"
                    : "=r"(a[i][0]), "=r"(a[i][1]), "=r"(a[i][2]), "=r"(a[i][3])
                    : "r"(addr));
            }
            uint32_t b[8][2];
            #pragma unroll
            for (int jp = 0; jp < 4; jp++) {
                int row = wn * 64 + jp * 16 + ((lane >> 4) << 3) + (lane & 7);
                int ch = (ks * 2 + ((lane >> 3) & 1)) ^ (row & 7);
                uint32_t addr = bsbase + row * 128 + (ch << 4);
                asm volatile("ldmatrix.sync.aligned.m8n8.x4.shared.b16 {%0,%1,%2,%3}, [%4];"
                    : "=r"(b[2*jp][0]), "=r"(b[2*jp][1]), "=r"(b[2*jp+1][0]), "=r"(b[2*jp+1][1])
                    : "r"(addr));
            }
            #pragma unroll
            for (int i = 0; i < 2; i++)
                #pragma unroll
                for (int j = 0; j < 8; j++)
                    asm volatile("mma.sync.aligned.m16n8k16.row.col.f32.bf16.bf16.f32 "
                        "{%0,%1,%2,%3}, {%4,%5,%6,%7}, {%8,%9}, {%0,%1,%2,%3};"
                        : "+f"(d[i][j][0]), "+f"(d[i][j][1]), "+f"(d[i][j][2]), "+f"(d[i][j][3])
                        : "r"(a[i][0]), "r"(a[i][1]), "r"(a[i][2]), "r"(a[i][3]),
                          "r"(b[j][0]), "r"(b[j][1]));
        }
    }

    // scores (atomic-free, unchanged) + per-row tile max into shared
    #pragma unroll
    for (int i = 0; i < 2; i++) {
        int gm = m_base + wm * 32 + i * 16 + (lane >> 2);
        #pragma unroll
        for (int j = 0; j < 8; j++) {
            int gn = n_base + wn * 64 + j * 8 + (lane & 3) * 2;
            *(float2*)&g_scores[(size_t)gm * N_POOL + gn] = make_float2(d[i][j][0], d[i][j][1]);
            *(float2*)&g_scores[(size_t)(gm + 8) * N_POOL + gn] = make_float2(d[i][j][2], d[i][j][3]);
        }
        #pragma unroll
        for (int r = 0; r < 2; r++) {
            const int srow_loc = wm * 32 + i * 16 + r * 8 + (lane >> 2);
            float vmax = -1e30f;
            #pragma unroll
            for (int j = 0; j < 8; j++)
                vmax = fmaxf(vmax, fmaxf(d[i][j][2*r], d[i][j][2*r + 1]));
            atomicMax(&sTmax[srow_loc], enc_mono(vmax));
        }
    }
    __syncthreads();
    if (t < GBM)
        g_tmax[(size_t)(m_base + t) * N_TILES + (wid >> 4)] = sTmax[t];
}

// ---------------------------------------------------------------------------
// Kernel 3: dedicated lean streaming copy (8-deep bursts; measured best).
// ---------------------------------------------------------------------------
__global__ void __launch_bounds__(256)
copy_kernel(const float4* __restrict__ src, float4* __restrict__ dst)
{
    long long base = (long long)blockIdx.x * (256 * CPY_PER_THREAD) + threadIdx.x;
    #pragma unroll 1
    for (int it = 0; it < CPY_PER_THREAD / 8; it++) {       // 16 iterations
        float4 c[8];
        #pragma unroll
        for (int j = 0; j < 8; j++) c[j] = __ldcs(&src[base + (long long)j * 256]);
        #pragma unroll
        for (int j = 0; j < 8; j++) __stcs(&dst[base + (long long)j * 256], c[j]);
        base += 8LL * 256;
    }
}

// ---------------------------------------------------------------------------
// Kernel 4: rowmax from 32 tile-maxes (128B, not a 16KB scan), candidate
// compaction from only the qualifying tiles, warp-cooperative fp32 rescore,
// exact argmax (first-index tie-break), gather Ek/Ev. Candidate set is
// provably identical to the validated full-scan version.
// ---------------------------------------------------------------------------
__global__ void __launch_bounds__(256)
rescore_gather_kernel(const float* __restrict__ xq, const float* __restrict__ ek,
                      const float* __restrict__ ep, float* __restrict__ out)
{
    const int b = blockIdx.x;
    const int t = threadIdx.x;
    const int warp = t >> 5, lane = t & 31;
    const float* __restrict__ srow = g_scores + (size_t)b * N_POOL;

    __shared__ unsigned long long sbest;
    __shared__ int scnt;
    __shared__ int cand[N_POOL];   // capacity == pool size: cannot overflow

    // rowmax from per-tile maxima (every warp loads all 32)
    unsigned tm = g_tmax[(size_t)b * N_TILES + lane];
    float tv = dec_mono(tm);
    #pragma unroll
    for (int o = 16; o; o >>= 1) tv = fmaxf(tv, __shfl_xor_sync(0xffffffffu, tv, o));
    const float thresh = tv - TAU;

    if (t == 0) { sbest = 0ull; scnt = 0; }
    __syncthreads();

    // scan only tiles whose max can reach the threshold (typically 1-3 of 32)
    #pragma unroll 1
    for (int tile = 0; tile < N_TILES; tile++) {
        float tmax_v = dec_mono(__shfl_sync(0xffffffffu, tm, tile));
        if (tmax_v < thresh) continue;            // uniform across block
        if (t < GBN) {
            float v = srow[tile * GBN + t];
            if (v >= thresh) {
                int p = atomicAdd(&scnt, 1);
                cand[p] = tile * GBN + t;
            }
        }
    }
    __syncthreads();

    const float4* __restrict__ qr = (const float4*)(xq + (size_t)b * K_DIM);
    float4 q[6];
    #pragma unroll
    for (int i = 0; i < 6; i++) q[i] = qr[lane + i * 32];

    const int cnt = scnt;
    for (int c = warp; c < cnt; c += 8) {
        const int n = cand[c];
        const float4* __restrict__ er = (const float4*)(ek + (size_t)n * K_DIM);
        float s = 0.f;
        #pragma unroll
        for (int i = 0; i < 6; i++) {
            float4 e = er[lane + i * 32];
            s += e.x*q[i].x + e.y*q[i].y + e.z*q[i].z + e.w*q[i].w;
        }
        #pragma unroll
        for (int o = 16; o; o >>= 1) s += __shfl_xor_sync(0xffffffffu, s, o);
        if (lane == 0) {
            float val = s * g_rinv[n];
            unsigned long long key =
                ((unsigned long long)enc_mono(val) << 32) |
                (unsigned long long)(0xFFFFFFFFu - (unsigned)n);
            atomicMax(&sbest, key);
        }
    }
    __syncthreads();

    const unsigned idx = 0xFFFFFFFFu - (unsigned)(sbest & 0xFFFFFFFFull);

    const float4* __restrict__ src = (const float4*)(ep + (size_t)idx * (EP_LEN * K_DIM));
    float4* dEk = (float4*)out + (size_t)b * (4 * K_DIM / 4);
    float4* dEv = (float4*)(out + EKV_ELEMS) + (size_t)b * (4 * K_DIM / 4);
    #pragma unroll
    for (int j = t; j < 768; j += 256) dEk[j] = src[j];
    #pragma unroll
    for (int j = t; j < 768; j += 256) dEv[j] = src[768 + j];
}

// ---------------------------------------------------------------------------
// Launch: fork/join overlap; copy on LOW priority so chain blocks get SM
// slots promptly (compresses the contention window).
// ---------------------------------------------------------------------------
extern "C" void kernel_launch(void* const* d_in, const int* in_sizes, int n_in,
                              void* d_out, int out_size)
{
    const float *xq = nullptr, *xb = nullptr, *ek = nullptr, *ep = nullptr;
    for (int i = 0; i < n_in; i++) {
        long long sz = in_sizes[i];
        if      (sz == (long long)M_ROWS * K_DIM)          xq = (const float*)d_in[i];
        else if (sz == XB_ELEMS)                           xb = (const float*)d_in[i];
        else if (sz == (long long)N_POOL * K_DIM)          ek = (const float*)d_in[i];
        else if (sz == (long long)N_POOL * EP_LEN * K_DIM) ep = (const float*)d_in[i];
        // 'l' (size 1) ignored: e_p.shape[1]//2 == 4 regardless of l in {3,4,5}
    }
    float* out = (float*)d_out;

    int prLo, prHi;
    cudaDeviceGetStreamPriorityRange(&prLo, &prHi);
    cudaStream_t s2;
    cudaStreamCreateWithPriority(&s2, cudaStreamNonBlocking, prLo);  // low priority
    cudaEvent_t eFork, eJoin;
    cudaEventCreateWithFlags(&eFork, cudaEventDisableTiming);
    cudaEventCreateWithFlags(&eJoin, cudaEventDisableTiming);

    // fork: copy runs on s2, rooted in the capture stream
    cudaEventRecord(eFork, 0);
    cudaStreamWaitEvent(s2, eFork, 0);
    copy_kernel<<<COPY_BLOCKS, 256, 0, s2>>>((const float4*)xb,
                                             (float4*)(out + 2 * EKV_ELEMS));

    // main chain on the capture stream
    prep_kernel<<<768, 256>>>(xq, ek);
    gemm_kernel<<<GEMM_BLOCKS, 256>>>();
    rescore_gather_kernel<<<M_ROWS, 256>>>(xq, ek, ep, out);

    // join: capture stream waits for the copy branch
    cudaEventRecord(eJoin, s2);
    cudaStreamWaitEvent(0, eJoin, 0);
}

// round 14
// speedup vs baseline: 1.0258x; 1.0258x over previous
#include <cuda_runtime.h>
#include <cuda_bf16.h>
#include <stdint.h>

// Fixed problem shapes
#define M_ROWS   2048
#define N_POOL   4096
#define K_DIM    768
#define EP_LEN   8
#define XB_ELEMS 309854208LL   // 2048*197*768
#define EKV_ELEMS 6291456LL    // 2048*4*768

// GEMM tiling (tensor-core bf16)
#define GBM 128
#define GBN 128
#define GBK 64
#define GEMM_BLOCKS 512        // (2048/128)*(4096/128)

// Copy: exact division — 77,463,552 float4 = 2364 blocks * 256 thr * 128 f4
#define COPY_BLOCKS 2364
#define CPY_PER_THREAD 128     // 16 iterations of 8 (measured-best config)

#define TAU 0.01f              // > 2x worst-case bf16 mma score error (~0.008)

// Device-global scratch (static allocation — allowed)
__device__ float g_rinv[N_POOL];
__device__ __align__(16) __nv_bfloat16 g_nkbf[N_POOL * K_DIM];   // normalized e_k, bf16
__device__ __align__(16) __nv_bfloat16 g_qbf[M_ROWS * K_DIM];    // normalized q, bf16
__device__ float g_scores[(size_t)M_ROWS * N_POOL];              // approx cos sims

// ---------------------------------------------------------------------------
// Kernel 1: normalize e_k / x_querry -> bf16, store 1/||e_k||.
// One warp per row; 6144 warps == N_POOL + M_ROWS rows exactly.
// ---------------------------------------------------------------------------
__global__ void __launch_bounds__(256)
prep_kernel(const float* __restrict__ xq, const float* __restrict__ ek)
{
    const int t = threadIdx.x;
    const int warp = (blockIdx.x * blockDim.x + t) >> 5;
    const int lane = t & 31;

    const bool is_ek = (warp < N_POOL);
    const int row = is_ek ? warp : warp - N_POOL;
    const float* src = (is_ek ? ek : xq) + (size_t)row * K_DIM;
    __nv_bfloat16* dst = (is_ek ? g_nkbf : g_qbf) + (size_t)row * K_DIM;

    float4 v[6];
    float s = 0.f;
    #pragma unroll
    for (int i = 0; i < 6; i++) {
        v[i] = ((const float4*)src)[lane + i * 32];
        s += v[i].x*v[i].x + v[i].y*v[i].y + v[i].z*v[i].z + v[i].w*v[i].w;
    }
    #pragma unroll
    for (int o = 16; o; o >>= 1) s += __shfl_xor_sync(0xffffffffu, s, o);
    float rinv = 1.0f / fmaxf(sqrtf(s), 1e-12f);
    if (is_ek && lane == 0) g_rinv[row] = rinv;

    #pragma unroll
    for (int i = 0; i < 6; i++) {
        __nv_bfloat162 lo = __floats2bfloat162_rn(v[i].x * rinv, v[i].y * rinv);
        __nv_bfloat162 hi = __floats2bfloat162_rn(v[i].z * rinv, v[i].w * rinv);
        uint2 u;
        u.x = *(unsigned*)&lo;
        u.y = *(unsigned*)&hi;
        ((uint2*)dst)[lane + i * 32] = u;
    }
}

// ---------------------------------------------------------------------------
// Kernel 2: standalone bf16 mma.sync GEMM -> g_scores (fp32, atomic-free
// epilogue — measured faster than every fused-argmax variant tried).
// 128x128 tile, 8 warps (4x2), warp computes 32x64; one-K-tile prefetch.
// ---------------------------------------------------------------------------
__global__ void __launch_bounds__(256)
gemm_kernel()
{
    __shared__ __align__(16) __nv_bfloat16 As[GBM * GBK];
    __shared__ __align__(16) __nv_bfloat16 Bs[GBN * GBK];
    uint4* As4 = (uint4*)As;
    uint4* Bs4 = (uint4*)Bs;

    const int wid = blockIdx.x;
    const int m_base = (wid & 15) * GBM;
    const int n_base = (wid >> 4) * GBN;
    const int t = threadIdx.x;
    const int warp = t >> 5, lane = t & 31;
    const int wm = warp >> 1, wn = warp & 1;

    const uint4* __restrict__ gA = (const uint4*)g_qbf;   // row stride 96 uint4
    const uint4* __restrict__ gB = (const uint4*)g_nkbf;

    uint32_t asbase = (uint32_t)__cvta_generic_to_shared(As);
    uint32_t bsbase = (uint32_t)__cvta_generic_to_shared(Bs);

    float d[2][8][4];
    #pragma unroll
    for (int i = 0; i < 2; i++)
        #pragma unroll
        for (int j = 0; j < 8; j++)
            #pragma unroll
            for (int q = 0; q < 4; q++) d[i][j][q] = 0.f;

    int lrow[4], lch[4];
    #pragma unroll
    for (int p = 0; p < 4; p++) {
        int id = p * 256 + t;
        lrow[p] = id >> 3;
        lch[p]  = id & 7;
    }

    uint4 va[4], vb[4];
    #pragma unroll
    for (int p = 0; p < 4; p++) {
        va[p] = gA[(size_t)(m_base + lrow[p]) * 96 + lch[p]];
        vb[p] = gB[(size_t)(n_base + lrow[p]) * 96 + lch[p]];
    }

    for (int k0 = 0; k0 < K_DIM; k0 += GBK) {
        __syncthreads();
        #pragma unroll
        for (int p = 0; p < 4; p++) {
            As4[lrow[p] * 8 + (lch[p] ^ (lrow[p] & 7))] = va[p];
            Bs4[lrow[p] * 8 + (lch[p] ^ (lrow[p] & 7))] = vb[p];
        }
        __syncthreads();

        if (k0 + GBK < K_DIM) {
            const int kc = (k0 + GBK) >> 3;
            #pragma unroll
            for (int p = 0; p < 4; p++) {
                va[p] = gA[(size_t)(m_base + lrow[p]) * 96 + kc + lch[p]];
                vb[p] = gB[(size_t)(n_base + lrow[p]) * 96 + kc + lch[p]];
            }
        }

        #pragma unroll
        for (int ks = 0; ks < 4; ks++) {
            uint32_t a[2][4];
            #pragma unroll
            for (int i = 0; i < 2; i++) {
                int row = wm * 32 + i * 16 + (lane & 15);
                int ch = (ks * 2 + (lane >> 4)) ^ (row & 7);
                uint32_t addr = asbase + row * 128 + (ch << 4);
                asm volatile("ldmatrix.sync.aligned.m8n8.x4.shared.b16 {%0,%1,%2,%3}, [%4];"
                    : "=r"(a[i][0]), "=r"(a[i][1]), "=r"(a[i][2]), "=r"(a[i][3])
                    : "r"(addr));
            }
            uint32_t b[8][2];
            #pragma unroll
            for (int jp = 0; jp < 4; jp++) {
                int row = wn * 64 + jp * 16 + ((lane >> 4) << 3) + (lane & 7);
                int ch = (ks * 2 + ((lane >> 3) & 1)) ^ (row & 7);
                uint32_t addr = bsbase + row * 128 + (ch << 4);
                asm volatile("ldmatrix.sync.aligned.m8n8.x4.shared.b16 {%0,%1,%2,%3}, [%4];"
                    : "=r"(b[2*jp][0]), "=r"(b[2*jp][1]), "=r"(b[2*jp+1][0]), "=r"(b[2*jp+1][1])
                    : "r"(addr));
            }
            #pragma unroll
            for (int i = 0; i < 2; i++)
                #pragma unroll
                for (int j = 0; j < 8; j++)
                    asm volatile("mma.sync.aligned.m16n8k16.row.col.f32.bf16.bf16.f32 "
                        "{%0,%1,%2,%3}, {%4,%5,%6,%7}, {%8,%9}, {%0,%1,%2,%3};"
                        : "+f"(d[i][j][0]), "+f"(d[i][j][1]), "+f"(d[i][j][2]), "+f"(d[i][j][3])
                        : "r"(a[i][0]), "r"(a[i][1]), "r"(a[i][2]), "r"(a[i][3]),
                          "r"(b[j][0]), "r"(b[j][1]));
        }
    }

    #pragma unroll
    for (int i = 0; i < 2; i++) {
        int gm = m_base + wm * 32 + i * 16 + (lane >> 2);
        #pragma unroll
        for (int j = 0; j < 8; j++) {
            int gn = n_base + wn * 64 + j * 8 + (lane & 3) * 2;
            *(float2*)&g_scores[(size_t)gm * N_POOL + gn] = make_float2(d[i][j][0], d[i][j][1]);
            *(float2*)&g_scores[(size_t)(gm + 8) * N_POOL + gn] = make_float2(d[i][j][2], d[i][j][3]);
        }
    }
}

// ---------------------------------------------------------------------------
// Kernel 3: dedicated lean streaming copy — contiguous 512KB chunk per block,
// 8 independent LDG.128 in flight per thread, streaming hints. Measured best.
// ---------------------------------------------------------------------------
__global__ void __launch_bounds__(256)
copy_kernel(const float4* __restrict__ src, float4* __restrict__ dst)
{
    long long base = (long long)blockIdx.x * (256 * CPY_PER_THREAD) + threadIdx.x;
    #pragma unroll 1
    for (int it = 0; it < CPY_PER_THREAD / 8; it++) {       // 16 iterations
        float4 c[8];
        #pragma unroll
        for (int j = 0; j < 8; j++) c[j] = __ldcs(&src[base + (long long)j * 256]);
        #pragma unroll
        for (int j = 0; j < 8; j++) __stcs(&dst[base + (long long)j * 256], c[j]);
        base += 8LL * 256;
    }
}

// ---------------------------------------------------------------------------
// Kernel 4: per-row approx max (full 256-thread scan — measured faster than
// tile-pruned variants) -> candidate compaction -> warp-cooperative fp32
// rescore -> exact argmax (first-index tie-break) -> gather e_p[idx] -> Ek/Ev.
// ---------------------------------------------------------------------------
__global__ void __launch_bounds__(256)
rescore_gather_kernel(const float* __restrict__ xq, const float* __restrict__ ek,
                      const float* __restrict__ ep, float* __restrict__ out)
{
    const int b = blockIdx.x;
    const int t = threadIdx.x;
    const int warp = t >> 5, lane = t & 31;
    const float* __restrict__ srow = g_scores + (size_t)b * N_POOL;

    __shared__ float smax[8];
    __shared__ unsigned long long sbest;
    __shared__ int scnt;
    __shared__ int cand[N_POOL];   // capacity == pool size: cannot overflow

    float sv[16];
    float lm = -1e30f;
    #pragma unroll
    for (int i = 0; i < 16; i++) {
        sv[i] = srow[t + i * 256];
        lm = fmaxf(lm, sv[i]);
    }
    #pragma unroll
    for (int o = 16; o; o >>= 1) lm = fmaxf(lm, __shfl_xor_sync(0xffffffffu, lm, o));
    if (lane == 0) smax[warp] = lm;
    if (t == 0) { sbest = 0ull; scnt = 0; }
    __syncthreads();

    float rowmax = smax[0];
    #pragma unroll
    for (int w = 1; w < 8; w++) rowmax = fmaxf(rowmax, smax[w]);
    const float thresh = rowmax - TAU;

    #pragma unroll
    for (int i = 0; i < 16; i++) {
        if (sv[i] >= thresh) {
            int p = atomicAdd(&scnt, 1);
            cand[p] = t + i * 256;
        }
    }
    __syncthreads();

    const float4* __restrict__ qr = (const float4*)(xq + (size_t)b * K_DIM);
    float4 q[6];
    #pragma unroll
    for (int i = 0; i < 6; i++) q[i] = qr[lane + i * 32];

    const int cnt = scnt;
    for (int c = warp; c < cnt; c += 8) {
        const int n = cand[c];
        const float4* __restrict__ er = (const float4*)(ek + (size_t)n * K_DIM);
        float s = 0.f;
        #pragma unroll
        for (int i = 0; i < 6; i++) {
            float4 e = er[lane + i * 32];
            s += e.x*q[i].x + e.y*q[i].y + e.z*q[i].z + e.w*q[i].w;
        }
        #pragma unroll
        for (int o = 16; o; o >>= 1) s += __shfl_xor_sync(0xffffffffu, s, o);
        if (lane == 0) {
            float val = s * g_rinv[n];
            unsigned u = __float_as_uint(val);
            u = (u & 0x80000000u) ? ~u : (u | 0x80000000u);   // order-monotonic
            unsigned long long key =
                ((unsigned long long)u << 32) | (unsigned long long)(0xFFFFFFFFu - (unsigned)n);
            atomicMax(&sbest, key);
        }
    }
    __syncthreads();

    const unsigned idx = 0xFFFFFFFFu - (unsigned)(sbest & 0xFFFFFFFFull);

    const float4* __restrict__ src = (const float4*)(ep + (size_t)idx * (EP_LEN * K_DIM));
    float4* dEk = (float4*)out + (size_t)b * (4 * K_DIM / 4);
    float4* dEv = (float4*)(out + EKV_ELEMS) + (size_t)b * (4 * K_DIM / 4);
    #pragma unroll
    for (int j = t; j < 768; j += 256) dEk[j] = src[j];
    #pragma unroll
    for (int j = t; j < 768; j += 256) dEv[j] = src[768 + j];
}

// ---------------------------------------------------------------------------
// Launch: fork/join stream overlap (default priority — measured best). The
// copy (writes out[2*EKV:], reads only xb) is independent of the
// prep->gemm->rescore chain (writes out[:2*EKV]), so the ~70us compute chain
// hides under the ~390us DRAM-bound copy.
// ---------------------------------------------------------------------------
extern "C" void kernel_launch(void* const* d_in, const int* in_sizes, int n_in,
                              void* d_out, int out_size)
{
    const float *xq = nullptr, *xb = nullptr, *ek = nullptr, *ep = nullptr;
    for (int i = 0; i < n_in; i++) {
        long long sz = in_sizes[i];
        if      (sz == (long long)M_ROWS * K_DIM)          xq = (const float*)d_in[i];
        else if (sz == XB_ELEMS)                           xb = (const float*)d_in[i];
        else if (sz == (long long)N_POOL * K_DIM)          ek = (const float*)d_in[i];
        else if (sz == (long long)N_POOL * EP_LEN * K_DIM) ep = (const float*)d_in[i];
        // 'l' (size 1) ignored: e_p.shape[1]//2 == 4 regardless of l in {3,4,5}
    }
    float* out = (float*)d_out;

    cudaStream_t s2;
    cudaStreamCreateWithFlags(&s2, cudaStreamNonBlocking);
    cudaEvent_t eFork, eJoin;
    cudaEventCreateWithFlags(&eFork, cudaEventDisableTiming);
    cudaEventCreateWithFlags(&eJoin, cudaEventDisableTiming);

    // fork: copy runs on s2, rooted in the capture stream
    cudaEventRecord(eFork, 0);
    cudaStreamWaitEvent(s2, eFork, 0);
    copy_kernel<<<COPY_BLOCKS, 256, 0, s2>>>((const float4*)xb,
                                             (float4*)(out + 2 * EKV_ELEMS));

    // main chain on the capture stream
    prep_kernel<<<768, 256>>>(xq, ek);
    gemm_kernel<<<GEMM_BLOCKS, 256>>>();
    rescore_gather_kernel<<<M_ROWS, 256>>>(xq, ek, ep, out);

    // join: capture stream waits for the copy branch
    cudaEventRecord(eJoin, s2);
    cudaStreamWaitEvent(0, eJoin, 0);
}